// round 15
// baseline (speedup 1.0000x reference)
#include <cuda_runtime.h>
#include <cstdint>

// Unpool (stride-2 zero insertion):
//   in : (8, 256, 112, 112) fp32 -> out: (8, 256, 224, 224) fp32
//   out[..., ::2, ::2] = in, else 0.
//
// Floor model (confirmed over 11 rounds): traffic HW-pinned at ~455MB/replay
// (411MB writes + 44MB read misses immune to every cache policy); bench pins
// at 455MB / ~5.7TB/s sustained = 79.8-80.0us for every SM-efficient shape.
// Last lever: DRAM bus-turnaround separation. Two kernels in one capture:
//   1) zero_kernel: pure write stream (all odd output rows, 205MB, 0 reads)
//   2) copy_kernel: even rows (205MB writes + reads)
// Same total traffic; the pure-write phase eliminates read/write turnaround
// cycles at the HBM controller for half the volume.

namespace {
constexpr int W8_IN  = 14;   // 8-float chunks per 112-wide input row
constexpr int W4_OUT = 56;   // float4 per 224-wide output row
}

__device__ __forceinline__ void ldg256_evict_last(const void* p, float* v)
{
    asm volatile("ld.global.L2::evict_last.v8.f32 {%0,%1,%2,%3,%4,%5,%6,%7}, [%8];"
                 : "=f"(v[0]), "=f"(v[1]), "=f"(v[2]), "=f"(v[3]),
                   "=f"(v[4]), "=f"(v[5]), "=f"(v[6]), "=f"(v[7])
                 : "l"(p));
}

__device__ __forceinline__ void stg256_cs(void* p,
                                          float v0, float v1, float v2, float v3,
                                          float v4, float v5, float v6, float v7)
{
    asm volatile(
        "st.global.cs.v8.f32 [%0], {%1,%2,%3,%4,%5,%6,%7,%8};"
        :: "l"(p),
           "f"(v0), "f"(v1), "f"(v2), "f"(v3),
           "f"(v4), "f"(v5), "f"(v6), "f"(v7)
        : "memory");
}

// Kernel 1: pure write stream — zero all odd output rows.
// One thread per (input row, v8 chunk): two 256-bit zero stores (64B).
__global__ void __launch_bounds__(256)
zero_kernel(float4* __restrict__ out, int total)   // total = rows * 14
{
    int idx = blockIdx.x * blockDim.x + threadIdx.x;
    if (idx >= total) return;

    int irow = idx / W8_IN;
    int c    = idx - irow * W8_IN;

    float4* odd = out + (size_t)(2 * irow + 1) * W4_OUT + 4 * c;
    stg256_cs(odd,     0.f, 0.f, 0.f, 0.f, 0.f, 0.f, 0.f, 0.f);
    stg256_cs(odd + 2, 0.f, 0.f, 0.f, 0.f, 0.f, 0.f, 0.f, 0.f);
}

// Kernel 2: even rows — one v8 load (32B), two 256-bit interleaved stores (64B).
__global__ void __launch_bounds__(256)
copy_kernel(const float* __restrict__ x,
            float4* __restrict__ out, int total)   // total = rows * 14
{
    int idx = blockIdx.x * blockDim.x + threadIdx.x;
    if (idx >= total) return;

    int irow = idx / W8_IN;
    int c    = idx - irow * W8_IN;

    float a[8];
    ldg256_evict_last(x + (size_t)irow * 112 + c * 8, a);

    float4* even = out + (size_t)(2 * irow) * W4_OUT + 4 * c;
    stg256_cs(even,     a[0], 0.f, a[1], 0.f, a[2], 0.f, a[3], 0.f);
    stg256_cs(even + 2, a[4], 0.f, a[5], 0.f, a[6], 0.f, a[7], 0.f);
}

extern "C" void kernel_launch(void* const* d_in, const int* in_sizes, int n_in,
                              void* d_out, int out_size)
{
    const float* x = (const float*)d_in[0];
    float4* out = (float4*)d_out;

    // out_size = B*C*224*224 floats. Chunks = input floats / 8 = out_size / 32.
    int total = out_size / 32;

    const int threads = 256;
    int blocks = (total + threads - 1) / threads;

    zero_kernel<<<blocks, threads>>>(out, total);
    copy_kernel<<<blocks, threads>>>(x, out, total);
}

// round 16
// speedup vs baseline: 1.0036x; 1.0036x over previous
#include <cuda_runtime.h>
#include <cstdint>

// Unpool (stride-2 zero insertion):
//   in : (8, 256, 112, 112) fp32 -> out: (8, 256, 224, 224) fp32
//   out[..., ::2, ::2] = in, else 0.
//
// Floor model (confirmed over 11 rounds): traffic HW-pinned at ~455MB/replay
// (411MB writes + 44MB read misses immune to every cache policy); bench pins
// at 455MB / ~5.7TB/s sustained = 79.8-80.0us for every SM-efficient shape.
// Last lever: DRAM bus-turnaround separation. Two kernels in one capture:
//   1) zero_kernel: pure write stream (all odd output rows, 205MB, 0 reads)
//   2) copy_kernel: even rows (205MB writes + reads)
// Same total traffic; the pure-write phase eliminates read/write turnaround
// cycles at the HBM controller for half the volume.

namespace {
constexpr int W8_IN  = 14;   // 8-float chunks per 112-wide input row
constexpr int W4_OUT = 56;   // float4 per 224-wide output row
}

__device__ __forceinline__ void ldg256_evict_last(const void* p, float* v)
{
    asm volatile("ld.global.L2::evict_last.v8.f32 {%0,%1,%2,%3,%4,%5,%6,%7}, [%8];"
                 : "=f"(v[0]), "=f"(v[1]), "=f"(v[2]), "=f"(v[3]),
                   "=f"(v[4]), "=f"(v[5]), "=f"(v[6]), "=f"(v[7])
                 : "l"(p));
}

__device__ __forceinline__ void stg256_cs(void* p,
                                          float v0, float v1, float v2, float v3,
                                          float v4, float v5, float v6, float v7)
{
    asm volatile(
        "st.global.cs.v8.f32 [%0], {%1,%2,%3,%4,%5,%6,%7,%8};"
        :: "l"(p),
           "f"(v0), "f"(v1), "f"(v2), "f"(v3),
           "f"(v4), "f"(v5), "f"(v6), "f"(v7)
        : "memory");
}

// Kernel 1: pure write stream — zero all odd output rows.
// One thread per (input row, v8 chunk): two 256-bit zero stores (64B).
__global__ void __launch_bounds__(256)
zero_kernel(float4* __restrict__ out, int total)   // total = rows * 14
{
    int idx = blockIdx.x * blockDim.x + threadIdx.x;
    if (idx >= total) return;

    int irow = idx / W8_IN;
    int c    = idx - irow * W8_IN;

    float4* odd = out + (size_t)(2 * irow + 1) * W4_OUT + 4 * c;
    stg256_cs(odd,     0.f, 0.f, 0.f, 0.f, 0.f, 0.f, 0.f, 0.f);
    stg256_cs(odd + 2, 0.f, 0.f, 0.f, 0.f, 0.f, 0.f, 0.f, 0.f);
}

// Kernel 2: even rows — one v8 load (32B), two 256-bit interleaved stores (64B).
__global__ void __launch_bounds__(256)
copy_kernel(const float* __restrict__ x,
            float4* __restrict__ out, int total)   // total = rows * 14
{
    int idx = blockIdx.x * blockDim.x + threadIdx.x;
    if (idx >= total) return;

    int irow = idx / W8_IN;
    int c    = idx - irow * W8_IN;

    float a[8];
    ldg256_evict_last(x + (size_t)irow * 112 + c * 8, a);

    float4* even = out + (size_t)(2 * irow) * W4_OUT + 4 * c;
    stg256_cs(even,     a[0], 0.f, a[1], 0.f, a[2], 0.f, a[3], 0.f);
    stg256_cs(even + 2, a[4], 0.f, a[5], 0.f, a[6], 0.f, a[7], 0.f);
}

extern "C" void kernel_launch(void* const* d_in, const int* in_sizes, int n_in,
                              void* d_out, int out_size)
{
    const float* x = (const float*)d_in[0];
    float4* out = (float4*)d_out;

    // out_size = B*C*224*224 floats. Chunks = input floats / 8 = out_size / 32.
    int total = out_size / 32;

    const int threads = 256;
    int blocks = (total + threads - 1) / threads;

    zero_kernel<<<blocks, threads>>>(out, total);
    copy_kernel<<<blocks, threads>>>(x, out, total);
}